// round 13
// baseline (speedup 1.0000x reference)
#include <cuda_runtime.h>

// Fixed shapes: B=2, C=3, H=320, W=480
#define HH   320
#define WW   480
#define BB   2
#define HWP  (HH * WW)          // 153600
#define SPAN 11
#define NOFF 23
#define NOFF2 (NOFF * NOFF)     // 529
#define NROWS (BB * HH)         // 640

#define PADW 512                // padded row stride
#define PADH (HH + 2 * SPAN)    // 342
#define PADSZ (PADH * PADW)     // 175104 per batch

#define SMW   504               // staged window width (uint2)
#define WROWS 13                // window rows per dx-half (11 dx + 2 p-rows span)
#define SMCNT (WROWS * SMW)     // 6552 uint2 = 52416 B
#define NTHR  288               // 2 groups x 144 (132 live each)
#define GRP   144
#define LIVE  132               // 11 dx x 12 dy-pairs
#define LMAX  240               // max actives per row per parity
#define SMBYTES (SMCNT * 8 + 2 * SMW * 8 + 4 * LMAX * 2)   // 62400

#define NHALO 21504             // per batch: 342*512 - 320*480

// ---------------- scratch (static device globals) ----------------------------
__device__ uint2 g_pix8[BB * PADSZ];     // {r|g<<8|b<<16, y0|y1<<8|y2<<16 (|FF<<24 halo)}
__device__ float g_rps[HH][WW + 1];      // row prefix sums of M = sum_b (1-dst)
__device__ unsigned short g_actE[NROWS][LMAX]; // even-col active byte-offsets
__device__ unsigned short g_actO[NROWS][LMAX]; // odd-col active byte-offsets
__device__ int   g_cntE[NROWS];
__device__ int   g_cntO[NROWS];
__device__ float g_num[NOFF2];
__device__ float g_den[NOFF2];
__device__ float g_cep[HH];              // per-block CE partials
__device__ int   g_sync;                 // k_num completion counter (self-resetting)

// ---------------- helpers ----------------------------------------------------
__device__ __forceinline__ float warpReduceSum(float v) {
#pragma unroll
    for (int o = 16; o > 0; o >>= 1)
        v += __shfl_xor_sync(0xffffffffu, v, o);
    return v;
}

__device__ __forceinline__ float ex2f(float x) {
    float y;
    asm("ex2.approx.ftz.f32 %0, %1;" : "=f"(y) : "f"(x));
    return y;
}

// ---------------- kernel 1: prep (softmax/CE/pack/scan/lists + halo init) ------
__global__ void __launch_bounds__(480) k_prep(const float* __restrict__ logit,
                                              const float* __restrict__ image,
                                              const float* __restrict__ src,
                                              const float* __restrict__ dst,
                                              const int*   __restrict__ tgt) {
    __shared__ float s_wtot[15];
    __shared__ int   s_pcnt[BB][2][15];   // [batch][parity][warp]
    __shared__ float s_red[15];

    int i    = blockIdx.x;                // image row
    int j    = threadIdx.x;               // column
    int lane = j & 31;
    int w    = j >> 5;                    // warp 0..14
    int par  = j & 1;
    int idx  = i * WW + j;
    int pcol = (i + SPAN) * PADW + (j + SPAN);

    // ---- distributed halo init + accumulator zeroing (disjoint from interior)
    {
        int t = i * 480 + j;
        if (t < BB * NHALO) {
            int b = t / NHALO;
            int s = t - b * NHALO;
            int row, col;
            if (s < 11 * PADW) {                   // top halo rows 0..10
                row = s / PADW; col = s % PADW;
            } else if (s < 22 * PADW) {            // bottom halo rows 331..341
                int u = s - 11 * PADW;
                row = 331 + u / PADW; col = u % PADW;
            } else {                               // side cols of rows 11..330
                int u = s - 22 * PADW;
                row = 11 + u / 32;
                int c = u % 32;
                col = (c < 11) ? c : (480 + c);    // 0..10 and 491..511
            }
            uint2 v; v.x = 0u; v.y = 0xFF000000u;
            g_pix8[b * PADSZ + row * PADW + col] = v;
        }
        int t2 = t - BB * NHALO;
        if (t2 >= 0 && t2 < NOFF2) g_num[t2] = 0.0f;
    }

    float Msum = 0.0f, ceSum = 0.0f, dstSum = 0.0f;
    bool actv[BB];
#pragma unroll
    for (int b = 0; b < BB; b++) {
        int cb = b * 3 * HWP + idx;
        float l0 = logit[cb], l1 = logit[cb + HWP], l2 = logit[cb + 2 * HWP];
        float m  = fmaxf(l0, fmaxf(l1, l2));
        float e0 = __expf(l0 - m), e1 = __expf(l1 - m), e2 = __expf(l2 - m);
        float s  = e0 + e1 + e2;
        float inv = 1.0f / s;

        int   t  = tgt[b * HWP + idx];
        float lt = (t == 0) ? l0 : ((t == 1) ? l1 : l2);
        ceSum += m + __logf(s) - lt;

        float sv   = src[b * HWP + idx];
        float dv   = dst[b * HWP + idx];
        float mdst = 1.0f - dv;
        actv[b] = (sv * mdst) > 0.0f;

        float i0 = image[cb], i1 = image[cb + HWP], i2 = image[cb + 2 * HWP];
        unsigned r8 = __float2uint_rn(i0 * 255.0f);
        unsigned g8 = __float2uint_rn(i1 * 255.0f);
        unsigned b8 = __float2uint_rn(i2 * 255.0f);
        float y0 = e0 * inv, y1 = e1 * inv;
        int y0q = (int)__float2uint_rn(y0 * 255.0f);
        int y1q = (int)__float2uint_rn(y1 * 255.0f);
        int y2q = 255 - y0q - y1q;
        if (y2q < 0) y2q = 0;

        uint2 v;
        v.x = r8 | (g8 << 8) | (b8 << 16);
        v.y = (unsigned)y0q | ((unsigned)y1q << 8) | ((unsigned)y2q << 16);
        g_pix8[b * PADSZ + pcol] = v;      // byte3 of .y = 0 -> valid

        dstSum += dv;
        Msum   += mdst;
    }

    // ---- row inclusive prefix scan of Msum -> g_rps[i][*] ----
    float v = Msum;
#pragma unroll
    for (int o = 1; o < 32; o <<= 1) {
        float u = __shfl_up_sync(0xffffffffu, v, o);
        if (lane >= o) v += u;
    }
    if (lane == 31) s_wtot[w] = v;

    // ---- per (batch,parity) active ballots ----
    unsigned balE[BB], balO[BB];
#pragma unroll
    for (int b = 0; b < BB; b++) {
        balE[b] = __ballot_sync(0xffffffffu, actv[b] && par == 0);
        balO[b] = __ballot_sync(0xffffffffu, actv[b] && par == 1);
        if (lane == 0) {
            s_pcnt[b][0][w] = __popc(balE[b]);
            s_pcnt[b][1][w] = __popc(balO[b]);
        }
    }
    __syncthreads();

    if (j == 0) {
        float acc = 0.0f;
#pragma unroll
        for (int k = 0; k < 15; k++) { float c = s_wtot[k]; s_wtot[k] = acc; acc += c; }
#pragma unroll
        for (int b = 0; b < BB; b++) {
            int ie = 0, io = 0;
#pragma unroll
            for (int k = 0; k < 15; k++) {
                int ce = s_pcnt[b][0][k]; s_pcnt[b][0][k] = ie; ie += ce;
                int co = s_pcnt[b][1][k]; s_pcnt[b][1][k] = io; io += co;
            }
            g_cntE[b * HH + i] = ie;
            g_cntO[b * HH + i] = io;
        }
    }
    __syncthreads();

    if (j == 0) g_rps[i][0] = 0.0f;
    g_rps[i][j + 1] = v + s_wtot[w];

#pragma unroll
    for (int b = 0; b < BB; b++) {
        if (actv[b]) {
            unsigned bal = par ? balO[b] : balE[b];
            int pos = s_pcnt[b][par][w] + __popc(bal & ((1u << lane) - 1u));
            if (par) g_actO[b * HH + i][pos] = (unsigned short)(j << 3);
            else     g_actE[b * HH + i][pos] = (unsigned short)(j << 3);
        }
    }

    float pr = warpReduceSum(ceSum * dstSum);
    if (lane == 0) s_red[w] = pr;
    __syncthreads();
    if (w == 0) {
        float t2 = (lane < 15) ? s_red[lane] : 0.0f;
        t2 = warpReduceSum(t2);
        if (lane == 0) g_cep[i] = t2;
    }
}

// ---------------- kernel 2: denominators (warp per offset, rectangle sums) -----
__global__ void k_den() {               // grid=36, block=480
    int w    = blockIdx.x * 15 + (threadIdx.x >> 5);
    int lane = threadIdx.x & 31;
    if (w >= NOFF2) return;
    int dx = w / NOFF - SPAN;
    int dy = w % NOFF - SPAN;
    int r0 = (dx < 0) ? -dx : 0;
    int r1 = (dx > 0) ? HH - dx : HH;
    int c0 = (dy < 0) ? -dy : 0;
    int c1 = (dy > 0) ? WW - dy : WW;
    float s = 0.0f;
    for (int i = r0 + lane; i < r1; i += 32)
        s += g_rps[i][c1] - g_rps[i][c0];
    float tot = warpReduceSum(s);
    if (lane == 0) g_den[w] = tot;
}

// ---------------- numerator sweep (template on parity group) --------------------
// Core eval: 8 inst — dp4a folds the 0x4B000000 magic directly (s2, dp < 2^23).
// G=0: even pixels, E0 -> A (dyA=2m-11), E1 -> X (dyA+1)
// G=1: odd pixels,  E0 -> X (dyA-1),     E1 -> A
template<int G>
__device__ __forceinline__ void sweep2(const char* pb, const char* qb,
                                       const unsigned short* sal, int cnt,
                                       float& accA, float& stvA,
                                       float& accX, float& stvX) {
    const double KCd = -50.0 * 1.4426950408889634 / 65025.0;
    const float  KC  = (float)KCd;
    const float  KB  = (float)(-(double)KC * 8388608.0);
    const float  C1  = 8453633.0f;                 // 2^23 + 65025 (exact)
    const unsigned MAGIC = 0x4B000000u;
    const unsigned* sal32 = (const unsigned*)sal;

    int t = 0;
#pragma unroll 1
    for (; t + 2 <= cnt; t += 2) {
        unsigned pr = sal32[t >> 1];
        int ca = pr & 0xFFFFu;
        int cb = pr >> 16;
        uint2 p0 = *(const uint2*)(pb + ca);
        uint4 q0 = *(const uint4*)(qb + ca);
        uint2 p1 = *(const uint2*)(pb + cb);
        uint4 q1 = *(const uint4*)(qb + cb);

        unsigned d00  = __vabsdiffu4(p0.x, q0.x);
        unsigned s200 = __dp4a(d00, d00, MAGIC);
        unsigned dp00 = __dp4a(p0.y, q0.y, MAGIC);
        float k00  = ex2f(fmaf(__uint_as_float(s200), KC, KB));
        float tv00 = C1 - __uint_as_float(dp00);
        unsigned d01  = __vabsdiffu4(p0.x, q0.z);
        unsigned s201 = __dp4a(d01, d01, MAGIC);
        unsigned dp01 = __dp4a(p0.y, q0.w, MAGIC);
        float k01  = ex2f(fmaf(__uint_as_float(s201), KC, KB));
        float tv01 = C1 - __uint_as_float(dp01);
        unsigned d10  = __vabsdiffu4(p1.x, q1.x);
        unsigned s210 = __dp4a(d10, d10, MAGIC);
        unsigned dp10 = __dp4a(p1.y, q1.y, MAGIC);
        float k10  = ex2f(fmaf(__uint_as_float(s210), KC, KB));
        float tv10 = C1 - __uint_as_float(dp10);
        unsigned d11  = __vabsdiffu4(p1.x, q1.z);
        unsigned s211 = __dp4a(d11, d11, MAGIC);
        unsigned dp11 = __dp4a(p1.y, q1.w, MAGIC);
        float k11  = ex2f(fmaf(__uint_as_float(s211), KC, KB));
        float tv11 = C1 - __uint_as_float(dp11);

        if (G == 0) {
            accA = fmaf(k00, tv00, accA); stvA += tv00;
            accX = fmaf(k01, tv01, accX); stvX += tv01;
            accA = fmaf(k10, tv10, accA); stvA += tv10;
            accX = fmaf(k11, tv11, accX); stvX += tv11;
        } else {
            accX = fmaf(k00, tv00, accX); stvX += tv00;
            accA = fmaf(k01, tv01, accA); stvA += tv01;
            accX = fmaf(k10, tv10, accX); stvX += tv10;
            accA = fmaf(k11, tv11, accA); stvA += tv11;
        }
    }
    if (t < cnt) {
        int ca = sal[t];
        uint2 p0 = *(const uint2*)(pb + ca);
        uint4 q0 = *(const uint4*)(qb + ca);
        unsigned d00  = __vabsdiffu4(p0.x, q0.x);
        unsigned s200 = __dp4a(d00, d00, MAGIC);
        unsigned dp00 = __dp4a(p0.y, q0.y, MAGIC);
        float k00  = ex2f(fmaf(__uint_as_float(s200), KC, KB));
        float tv00 = C1 - __uint_as_float(dp00);
        unsigned d01  = __vabsdiffu4(p0.x, q0.z);
        unsigned s201 = __dp4a(d01, d01, MAGIC);
        unsigned dp01 = __dp4a(p0.y, q0.w, MAGIC);
        float k01  = ex2f(fmaf(__uint_as_float(s201), KC, KB));
        float tv01 = C1 - __uint_as_float(dp01);
        if (G == 0) {
            accA = fmaf(k00, tv00, accA); stvA += tv00;
            accX = fmaf(k01, tv01, accX); stvX += tv01;
        } else {
            accX = fmaf(k00, tv00, accX); stvX += tv00;
            accA = fmaf(k01, tv01, accA); stvA += tv01;
        }
    }
}

// ---------------- kernel 3: numerators + fused finalize --------------------------
// Block = (row-pair, dx-half): 640 blocks, 13 staged window rows (52 KB) ->
// 3 blocks/SM resident, ~4.3 waves: fine-grained tail, better latency hiding.
// Group 0 sweeps even-column actives, group 1 odd-column; thread owns
// (dx, dy-pair m) within its half; one aligned LDS.128 covers 2 dy bins.
// Last of the 640 blocks performs the finalize and writes out[0].
__global__ void __launch_bounds__(NTHR) k_num(float* __restrict__ out) {
    extern __shared__ char smraw[];
    uint2* sm = (uint2*)smraw;                         // [13][SMW]
    uint2* pm = sm + SMCNT;                            // [2][SMW] masked p rows
    unsigned short* slE0 = (unsigned short*)(pm + 2 * SMW);
    unsigned short* slE1 = slE0 + LMAX;
    unsigned short* slO0 = slE1 + LMAX;
    unsigned short* slO1 = slO0 + LMAX;
    __shared__ int s_last;
    __shared__ float s_fin[NTHR / 32];

    int bid  = blockIdx.x;                             // 0..639
    int rid2 = bid >> 1;                               // row-pair 0..319
    int h    = bid & 1;                                // 0: dx<0, 1: dx>0
    int b    = rid2 / (HH / 2);
    int rp   = rid2 - b * (HH / 2);
    int r0   = rp * 2;
    int rid0 = b * HH + r0;
    int cE0 = g_cntE[rid0], cE1 = g_cntE[rid0 + 1];
    int cO0 = g_cntO[rid0], cO1 = g_cntO[rid0 + 1];
    int tid = threadIdx.x;

    int base_off = h * SPAN;                           // window row 0 = padded r0+base_off
    const uint2* grow = g_pix8 + (b * PADSZ + (r0 + base_off) * PADW);

    // stage 13 window rows
    for (int t = tid; t < SMCNT; t += NTHR) {
        int rr = t / SMW;
        int c  = t - rr * SMW;
        sm[t] = grow[rr * PADW + c];
    }
    // masked p rows (padded rows r0+SPAN, r0+SPAN+1)
    {
        int poff = (SPAN - base_off) * PADW;
        for (int c = tid; c < SMW; c += NTHR) {
            uint2 v0 = grow[poff + c];        v0.y |= 0xFF000000u; pm[c] = v0;
            uint2 v1 = grow[poff + PADW + c]; v1.y |= 0xFF000000u; pm[SMW + c] = v1;
        }
    }
    for (int t = tid; t < cE0; t += NTHR) slE0[t] = g_actE[rid0][t];
    for (int t = tid; t < cE1; t += NTHR) slE1[t] = g_actE[rid0 + 1][t];
    for (int t = tid; t < cO0; t += NTHR) slO0[t] = g_actO[rid0][t];
    for (int t = tid; t < cO1; t += NTHR) slO1[t] = g_actO[rid0 + 1][t];
    __syncthreads();

    int g = tid / GRP;                                 // 0 even, 1 odd pixels
    int u = tid - g * GRP;
    if (u < LIVE) {                                    // dead lanes skip sweep
        int dxi = u / 12;                              // 0..10
        int m   = u - dxi * 12;                        // 0..11 (dy-pair)
        int dx  = h ? (dxi + 1) : (dxi - SPAN);        // h=0: -11..-1, h=1: 1..11

        const char* pb0 = (const char*)pm + SPAN * 8;
        const char* qb0 = (const char*)sm
            + (((SPAN + dx - base_off) * SMW + 2 * m) * 8) - (g ? 8 : 0);

        float accA = 0.f, stvA = 0.f, accX = 0.f, stvX = 0.f;
        if (g == 0) {
            sweep2<0>(pb0, qb0, slE0, cE0, accA, stvA, accX, stvX);
            sweep2<0>(pb0 + SMW * 8, qb0 + SMW * 8, slE1, cE1, accA, stvA, accX, stvX);
        } else {
            sweep2<1>(pb0, qb0, slO0, cO0, accA, stvA, accX, stvX);
            sweep2<1>(pb0 + SMW * 8, qb0 + SMW * 8, slO1, cO1, accA, stvA, accX, stvX);
        }

        const float INV = 1.0f / 65025.0f;
        int dyA = 2 * m - SPAN;                        // odd, always live
        {
            float kxy = __expf((float)(dx * dx + dyA * dyA) * (-1.0f / 72.0f));
            atomicAdd(&g_num[(dx + SPAN) * NOFF + (dyA + SPAN)],
                      fmaf(kxy, stvA, accA) * INV);
        }
        int dyX = g ? (dyA - 1) : (dyA + 1);
        if (dyX != 0 && dyX >= -SPAN && dyX <= SPAN) {
            float kxy = __expf((float)(dx * dx + dyX * dyX) * (-1.0f / 72.0f));
            atomicAdd(&g_num[(dx + SPAN) * NOFF + (dyX + SPAN)],
                      fmaf(kxy, stvX, accX) * INV);
        }
    }

    // ---- last-block finalize ----
    __threadfence();
    if (tid == 0)
        s_last = (atomicAdd(&g_sync, 1) == (int)gridDim.x - 1) ? 1 : 0;
    __syncthreads();
    if (!s_last) return;
    __threadfence();

    float v = 0.0f;
    for (int d = tid; d < NOFF2; d += NTHR) {
        int dx = d / NOFF - SPAN;
        int dy = d % NOFF - SPAN;
        if (dx != 0 && dy != 0)
            v += __fdividef(__ldcg(&g_num[d]), g_den[d]);
    }
    v *= (0.15f / (float)NOFF2);
    float ce = 0.0f;
    for (int t = tid; t < HH; t += NTHR) ce += g_cep[t];
    v += ce * (1.0f / ((float)BB * BB * HWP));

    int lane = tid & 31, w = tid >> 5;
    v = warpReduceSum(v);
    if (lane == 0) s_fin[w] = v;
    __syncthreads();
    if (w == 0) {
        float t2 = (lane < (NTHR >> 5)) ? s_fin[lane] : 0.0f;
        t2 = warpReduceSum(t2);
        if (lane == 0) {
            out[0] = t2;
            g_sync = 0;                                // reset for next replay
        }
    }
}

// ---------------- launch ----------------------------------------------------------
extern "C" void kernel_launch(void* const* d_in, const int* in_sizes, int n_in,
                              void* d_out, int out_size) {
    const float* logit = (const float*)d_in[0];
    const float* image = (const float*)d_in[1];
    const float* srcm  = (const float*)d_in[2];
    const float* dstm  = (const float*)d_in[3];
    const int*   tgt   = (const int*)d_in[4];
    float* out = (float*)d_out;

    cudaFuncSetAttribute(k_num, cudaFuncAttributeMaxDynamicSharedMemorySize, SMBYTES);

    k_prep<<<HH, 480>>>(logit, image, srcm, dstm, tgt);             // idx 0
    k_den<<<(NOFF2 + 14) / 15, 480>>>();                            // idx 1
    k_num<<<2 * (NROWS / 2), NTHR, SMBYTES>>>(out);                 // idx 2
}

// round 14
// speedup vs baseline: 1.1750x; 1.1750x over previous
#include <cuda_runtime.h>

// Fixed shapes: B=2, C=3, H=320, W=480
#define HH   320
#define WW   480
#define BB   2
#define HWP  (HH * WW)          // 153600
#define SPAN 11
#define NOFF 23
#define NOFF2 (NOFF * NOFF)     // 529
#define NROWS (BB * HH)         // 640

#define PADW 512                // padded row stride
#define PADH (HH + 2 * SPAN)    // 342
#define PADSZ (PADH * PADW)     // 175104 per batch

#define SMW   502               // staged window width (uint2; 502*8=4016, 16B mult)
#define ROWB  (SMW * 8)         // 4016 bytes per staged row
#define WROWS 25                // window rows: 3 p-rows + 2*SPAN
#define SMCNT (WROWS * SMW)     // 12550 uint2 = 100400 B
#define NTHR  576               // 2 groups x 288 (264 live each)
#define GRP   288
#define LIVE  264
#define LMAX  240               // max actives per row per parity
#define RPB   3                 // p-rows per block
#define BPB   107               // blocks per batch (ceil(320/3))
#define SMBYTES (SMCNT * 8 + RPB * ROWB + 2 * RPB * LMAX * 2)   // 115328

#define NHALO 21504             // per batch: 342*512 - 320*480

// ---------------- scratch (static device globals) ----------------------------
__device__ uint2 g_pix8[BB * PADSZ];     // {r|g<<8|b<<16, y0|y1<<8|y2<<16 (|FF<<24 halo)}
__device__ float g_rps[HH][WW + 1];      // row prefix sums of M = sum_b (1-dst)
__device__ unsigned short g_actE[NROWS][LMAX]; // even-col active byte-offsets
__device__ unsigned short g_actO[NROWS][LMAX]; // odd-col active byte-offsets
__device__ int   g_cntE[NROWS];
__device__ int   g_cntO[NROWS];
__device__ float g_num[NOFF2];
__device__ float g_den[NOFF2];
__device__ float g_cep[HH];              // per-block CE partials
__device__ int   g_sync;                 // k_num completion counter (self-resetting)

// ---------------- helpers ----------------------------------------------------
__device__ __forceinline__ float warpReduceSum(float v) {
#pragma unroll
    for (int o = 16; o > 0; o >>= 1)
        v += __shfl_xor_sync(0xffffffffu, v, o);
    return v;
}

__device__ __forceinline__ float ex2f(float x) {
    float y;
    asm("ex2.approx.ftz.f32 %0, %1;" : "=f"(y) : "f"(x));
    return y;
}

// ---------------- kernel 1: prep (softmax/CE/pack/scan/lists + halo init) ------
__global__ void __launch_bounds__(480) k_prep(const float* __restrict__ logit,
                                              const float* __restrict__ image,
                                              const float* __restrict__ src,
                                              const float* __restrict__ dst,
                                              const int*   __restrict__ tgt) {
    __shared__ float s_wtot[15];
    __shared__ int   s_pcnt[BB][2][15];   // [batch][parity][warp]
    __shared__ float s_red[15];

    int i    = blockIdx.x;                // image row
    int j    = threadIdx.x;               // column
    int lane = j & 31;
    int w    = j >> 5;                    // warp 0..14
    int par  = j & 1;
    int idx  = i * WW + j;
    int pcol = (i + SPAN) * PADW + (j + SPAN);

    // ---- distributed halo init + accumulator zeroing (disjoint from interior)
    {
        int t = i * 480 + j;
        if (t < BB * NHALO) {
            int b = t / NHALO;
            int s = t - b * NHALO;
            int row, col;
            if (s < 11 * PADW) {                   // top halo rows 0..10
                row = s / PADW; col = s % PADW;
            } else if (s < 22 * PADW) {            // bottom halo rows 331..341
                int u = s - 11 * PADW;
                row = 331 + u / PADW; col = u % PADW;
            } else {                               // side cols of rows 11..330
                int u = s - 22 * PADW;
                row = 11 + u / 32;
                int c = u % 32;
                col = (c < 11) ? c : (480 + c);    // 0..10 and 491..511
            }
            uint2 v; v.x = 0u; v.y = 0xFF000000u;
            g_pix8[b * PADSZ + row * PADW + col] = v;
        }
        int t2 = t - BB * NHALO;
        if (t2 >= 0 && t2 < NOFF2) g_num[t2] = 0.0f;
    }

    float Msum = 0.0f, ceSum = 0.0f, dstSum = 0.0f;
    bool actv[BB];
#pragma unroll
    for (int b = 0; b < BB; b++) {
        int cb = b * 3 * HWP + idx;
        float l0 = logit[cb], l1 = logit[cb + HWP], l2 = logit[cb + 2 * HWP];
        float m  = fmaxf(l0, fmaxf(l1, l2));
        float e0 = __expf(l0 - m), e1 = __expf(l1 - m), e2 = __expf(l2 - m);
        float s  = e0 + e1 + e2;
        float inv = 1.0f / s;

        int   t  = tgt[b * HWP + idx];
        float lt = (t == 0) ? l0 : ((t == 1) ? l1 : l2);
        ceSum += m + __logf(s) - lt;

        float sv   = src[b * HWP + idx];
        float dv   = dst[b * HWP + idx];
        float mdst = 1.0f - dv;
        actv[b] = (sv * mdst) > 0.0f;

        float i0 = image[cb], i1 = image[cb + HWP], i2 = image[cb + 2 * HWP];
        unsigned r8 = __float2uint_rn(i0 * 255.0f);
        unsigned g8 = __float2uint_rn(i1 * 255.0f);
        unsigned b8 = __float2uint_rn(i2 * 255.0f);
        float y0 = e0 * inv, y1 = e1 * inv;
        int y0q = (int)__float2uint_rn(y0 * 255.0f);
        int y1q = (int)__float2uint_rn(y1 * 255.0f);
        int y2q = 255 - y0q - y1q;
        if (y2q < 0) y2q = 0;

        uint2 v;
        v.x = r8 | (g8 << 8) | (b8 << 16);
        v.y = (unsigned)y0q | ((unsigned)y1q << 8) | ((unsigned)y2q << 16);
        g_pix8[b * PADSZ + pcol] = v;      // byte3 of .y = 0 -> valid

        dstSum += dv;
        Msum   += mdst;
    }

    // ---- row inclusive prefix scan of Msum -> g_rps[i][*] ----
    float v = Msum;
#pragma unroll
    for (int o = 1; o < 32; o <<= 1) {
        float u = __shfl_up_sync(0xffffffffu, v, o);
        if (lane >= o) v += u;
    }
    if (lane == 31) s_wtot[w] = v;

    // ---- per (batch,parity) active ballots ----
    unsigned balE[BB], balO[BB];
#pragma unroll
    for (int b = 0; b < BB; b++) {
        balE[b] = __ballot_sync(0xffffffffu, actv[b] && par == 0);
        balO[b] = __ballot_sync(0xffffffffu, actv[b] && par == 1);
        if (lane == 0) {
            s_pcnt[b][0][w] = __popc(balE[b]);
            s_pcnt[b][1][w] = __popc(balO[b]);
        }
    }
    __syncthreads();

    if (j == 0) {
        float acc = 0.0f;
#pragma unroll
        for (int k = 0; k < 15; k++) { float c = s_wtot[k]; s_wtot[k] = acc; acc += c; }
#pragma unroll
        for (int b = 0; b < BB; b++) {
            int ie = 0, io = 0;
#pragma unroll
            for (int k = 0; k < 15; k++) {
                int ce = s_pcnt[b][0][k]; s_pcnt[b][0][k] = ie; ie += ce;
                int co = s_pcnt[b][1][k]; s_pcnt[b][1][k] = io; io += co;
            }
            g_cntE[b * HH + i] = ie;
            g_cntO[b * HH + i] = io;
        }
    }
    __syncthreads();

    if (j == 0) g_rps[i][0] = 0.0f;
    g_rps[i][j + 1] = v + s_wtot[w];

#pragma unroll
    for (int b = 0; b < BB; b++) {
        if (actv[b]) {
            unsigned bal = par ? balO[b] : balE[b];
            int pos = s_pcnt[b][par][w] + __popc(bal & ((1u << lane) - 1u));
            if (par) g_actO[b * HH + i][pos] = (unsigned short)(j << 3);
            else     g_actE[b * HH + i][pos] = (unsigned short)(j << 3);
        }
    }

    float pr = warpReduceSum(ceSum * dstSum);
    if (lane == 0) s_red[w] = pr;
    __syncthreads();
    if (w == 0) {
        float t2 = (lane < 15) ? s_red[lane] : 0.0f;
        t2 = warpReduceSum(t2);
        if (lane == 0) g_cep[i] = t2;
    }
}

// ---------------- kernel 2: denominators (warp per offset, rectangle sums) -----
__global__ void k_den() {               // grid=36, block=480
    int w    = blockIdx.x * 15 + (threadIdx.x >> 5);
    int lane = threadIdx.x & 31;
    if (w >= NOFF2) return;
    int dx = w / NOFF - SPAN;
    int dy = w % NOFF - SPAN;
    int r0 = (dx < 0) ? -dx : 0;
    int r1 = (dx > 0) ? HH - dx : HH;
    int c0 = (dy < 0) ? -dy : 0;
    int c1 = (dy > 0) ? WW - dy : WW;
    float s = 0.0f;
    for (int i = r0 + lane; i < r1; i += 32)
        s += g_rps[i][c1] - g_rps[i][c0];
    float tot = warpReduceSum(s);
    if (lane == 0) g_den[w] = tot;
}

// ---------------- numerator sweep (template on parity group) --------------------
// Core eval: 8 inst — dp4a folds the 0x4B000000 magic directly (s2, dp < 2^23).
// G=0: even pixels, E0 -> A (dyA=2m-11), E1 -> X (dyA+1)
// G=1: odd pixels,  E0 -> X (dyA-1),     E1 -> A
template<int G>
__device__ __forceinline__ void sweep2(const char* pb, const char* qb,
                                       const unsigned short* sal, int cnt,
                                       float& accA, float& stvA,
                                       float& accX, float& stvX) {
    const double KCd = -50.0 * 1.4426950408889634 / 65025.0;
    const float  KC  = (float)KCd;
    const float  KB  = (float)(-(double)KC * 8388608.0);
    const float  C1  = 8453633.0f;                 // 2^23 + 65025 (exact)
    const unsigned MAGIC = 0x4B000000u;
    const unsigned* sal32 = (const unsigned*)sal;

    int t = 0;
#pragma unroll 1
    for (; t + 2 <= cnt; t += 2) {
        unsigned pr = sal32[t >> 1];
        int ca = pr & 0xFFFFu;
        int cb = pr >> 16;
        uint2 p0 = *(const uint2*)(pb + ca);
        uint4 q0 = *(const uint4*)(qb + ca);
        uint2 p1 = *(const uint2*)(pb + cb);
        uint4 q1 = *(const uint4*)(qb + cb);

        unsigned d00  = __vabsdiffu4(p0.x, q0.x);
        unsigned s200 = __dp4a(d00, d00, MAGIC);
        unsigned dp00 = __dp4a(p0.y, q0.y, MAGIC);
        float k00  = ex2f(fmaf(__uint_as_float(s200), KC, KB));
        float tv00 = C1 - __uint_as_float(dp00);
        unsigned d01  = __vabsdiffu4(p0.x, q0.z);
        unsigned s201 = __dp4a(d01, d01, MAGIC);
        unsigned dp01 = __dp4a(p0.y, q0.w, MAGIC);
        float k01  = ex2f(fmaf(__uint_as_float(s201), KC, KB));
        float tv01 = C1 - __uint_as_float(dp01);
        unsigned d10  = __vabsdiffu4(p1.x, q1.x);
        unsigned s210 = __dp4a(d10, d10, MAGIC);
        unsigned dp10 = __dp4a(p1.y, q1.y, MAGIC);
        float k10  = ex2f(fmaf(__uint_as_float(s210), KC, KB));
        float tv10 = C1 - __uint_as_float(dp10);
        unsigned d11  = __vabsdiffu4(p1.x, q1.z);
        unsigned s211 = __dp4a(d11, d11, MAGIC);
        unsigned dp11 = __dp4a(p1.y, q1.w, MAGIC);
        float k11  = ex2f(fmaf(__uint_as_float(s211), KC, KB));
        float tv11 = C1 - __uint_as_float(dp11);

        if (G == 0) {
            accA = fmaf(k00, tv00, accA); stvA += tv00;
            accX = fmaf(k01, tv01, accX); stvX += tv01;
            accA = fmaf(k10, tv10, accA); stvA += tv10;
            accX = fmaf(k11, tv11, accX); stvX += tv11;
        } else {
            accX = fmaf(k00, tv00, accX); stvX += tv00;
            accA = fmaf(k01, tv01, accA); stvA += tv01;
            accX = fmaf(k10, tv10, accX); stvX += tv10;
            accA = fmaf(k11, tv11, accA); stvA += tv11;
        }
    }
    if (t < cnt) {
        int ca = sal[t];
        uint2 p0 = *(const uint2*)(pb + ca);
        uint4 q0 = *(const uint4*)(qb + ca);
        unsigned d00  = __vabsdiffu4(p0.x, q0.x);
        unsigned s200 = __dp4a(d00, d00, MAGIC);
        unsigned dp00 = __dp4a(p0.y, q0.y, MAGIC);
        float k00  = ex2f(fmaf(__uint_as_float(s200), KC, KB));
        float tv00 = C1 - __uint_as_float(dp00);
        unsigned d01  = __vabsdiffu4(p0.x, q0.z);
        unsigned s201 = __dp4a(d01, d01, MAGIC);
        unsigned dp01 = __dp4a(p0.y, q0.w, MAGIC);
        float k01  = ex2f(fmaf(__uint_as_float(s201), KC, KB));
        float tv01 = C1 - __uint_as_float(dp01);
        if (G == 0) {
            accA = fmaf(k00, tv00, accA); stvA += tv00;
            accX = fmaf(k01, tv01, accX); stvX += tv01;
        } else {
            accX = fmaf(k00, tv00, accX); stvX += tv00;
            accA = fmaf(k01, tv01, accA); stvA += tv01;
        }
    }
}

// ---------------- kernel 3: numerators + fused finalize --------------------------
// Block = 3 p-rows of one batch: 214 blocks at 2/SM residency = SINGLE WAVE
// (no wave-quantization tail). Full 484-bin mapping per block (thread owns
// (dx, dy-pair)); one aligned LDS.128 covers 2 dy bins; sweep loops over the
// block's nr (2 or 3) rows. Last block performs the finalize.
__global__ void __launch_bounds__(NTHR) k_num(float* __restrict__ out) {
    extern __shared__ char smraw[];
    uint2* sm = (uint2*)smraw;                         // [25][SMW]
    uint2* pm = sm + SMCNT;                            // [RPB][SMW] masked p rows
    unsigned short* slE = (unsigned short*)(pm + RPB * SMW);  // [RPB][LMAX]
    unsigned short* slO = slE + RPB * LMAX;                   // [RPB][LMAX]
    __shared__ int s_last;
    __shared__ float s_fin[NTHR / 32];

    int bid = blockIdx.x;                              // 0..213
    int b   = bid / BPB;
    int rbk = bid - b * BPB;
    int i0  = rbk * RPB;                               // first image row
    int nr  = HH - i0; if (nr > RPB) nr = RPB;         // 3 (or 2 for last block)
    int rid0 = b * HH + i0;
    int tid = threadIdx.x;

    int cE[RPB], cO[RPB];
#pragma unroll
    for (int k = 0; k < RPB; k++) {
        cE[k] = (k < nr) ? g_cntE[rid0 + k] : 0;
        cO[k] = (k < nr) ? g_cntO[rid0 + k] : 0;
    }

    // stage window rows (padded rows i0 .. i0+nr+21)
    const uint2* grow = g_pix8 + (b * PADSZ + i0 * PADW);
    int nwr = nr + 22;
    for (int t = tid; t < nwr * SMW; t += NTHR) {
        int rr = t / SMW;
        int c  = t - rr * SMW;
        sm[rr * SMW + c] = grow[rr * PADW + c];
    }
    // masked p rows (padded rows i0+SPAN+k)
    for (int t = tid; t < nr * SMW; t += NTHR) {
        int k = t / SMW;
        int c = t - k * SMW;
        uint2 v = grow[(SPAN + k) * PADW + c];
        v.y |= 0xFF000000u;
        pm[k * SMW + c] = v;
    }
    for (int k = 0; k < nr; k++) {
        for (int t = tid; t < cE[k]; t += NTHR) slE[k * LMAX + t] = g_actE[rid0 + k][t];
        for (int t = tid; t < cO[k]; t += NTHR) slO[k * LMAX + t] = g_actO[rid0 + k][t];
    }
    __syncthreads();

    int g = tid / GRP;                                 // 0 even, 1 odd pixels
    int u = tid - g * GRP;
    if (u < LIVE) {                                    // dead lanes skip sweep
        int dxi = u / 12;                              // 0..21
        int m   = u - dxi * 12;                        // 0..11 (dy-pair)
        int dx  = (dxi < SPAN) ? dxi - SPAN : dxi - SPAN + 1;

        float accA = 0.f, stvA = 0.f, accX = 0.f, stvX = 0.f;
        const char* pmb = (const char*)pm + SPAN * 8;
        const char* smb = (const char*)sm
            + ((dx + SPAN) * SMW + 2 * m) * 8 - (g ? 8 : 0);
        const unsigned short* lst = g ? slO : slE;
        const int* cc = g ? cO : cE;

#pragma unroll 1
        for (int k = 0; k < nr; k++) {
            const char* pb = pmb + k * ROWB;
            const char* qb = smb + k * ROWB;
            if (g == 0) sweep2<0>(pb, qb, lst + k * LMAX, cc[k], accA, stvA, accX, stvX);
            else        sweep2<1>(pb, qb, lst + k * LMAX, cc[k], accA, stvA, accX, stvX);
        }

        const float INV = 1.0f / 65025.0f;
        int dyA = 2 * m - SPAN;                        // odd, always live
        {
            float kxy = __expf((float)(dx * dx + dyA * dyA) * (-1.0f / 72.0f));
            atomicAdd(&g_num[(dx + SPAN) * NOFF + (dyA + SPAN)],
                      fmaf(kxy, stvA, accA) * INV);
        }
        int dyX = g ? (dyA - 1) : (dyA + 1);
        if (dyX != 0 && dyX >= -SPAN && dyX <= SPAN) {
            float kxy = __expf((float)(dx * dx + dyX * dyX) * (-1.0f / 72.0f));
            atomicAdd(&g_num[(dx + SPAN) * NOFF + (dyX + SPAN)],
                      fmaf(kxy, stvX, accX) * INV);
        }
    }

    // ---- last-block finalize ----
    __threadfence();
    if (tid == 0)
        s_last = (atomicAdd(&g_sync, 1) == (int)gridDim.x - 1) ? 1 : 0;
    __syncthreads();
    if (!s_last) return;
    __threadfence();

    float v = 0.0f;
    for (int d = tid; d < NOFF2; d += NTHR) {
        int dx = d / NOFF - SPAN;
        int dy = d % NOFF - SPAN;
        if (dx != 0 && dy != 0)
            v += __fdividef(__ldcg(&g_num[d]), g_den[d]);
    }
    v *= (0.15f / (float)NOFF2);
    float ce = 0.0f;
    for (int t = tid; t < HH; t += NTHR) ce += g_cep[t];
    v += ce * (1.0f / ((float)BB * BB * HWP));

    int lane = tid & 31, w = tid >> 5;
    v = warpReduceSum(v);
    if (lane == 0) s_fin[w] = v;
    __syncthreads();
    if (w == 0) {
        float t2 = (lane < (NTHR >> 5)) ? s_fin[lane] : 0.0f;
        t2 = warpReduceSum(t2);
        if (lane == 0) {
            out[0] = t2;
            g_sync = 0;                                // reset for next replay
        }
    }
}

// ---------------- launch ----------------------------------------------------------
extern "C" void kernel_launch(void* const* d_in, const int* in_sizes, int n_in,
                              void* d_out, int out_size) {
    const float* logit = (const float*)d_in[0];
    const float* image = (const float*)d_in[1];
    const float* srcm  = (const float*)d_in[2];
    const float* dstm  = (const float*)d_in[3];
    const int*   tgt   = (const int*)d_in[4];
    float* out = (float*)d_out;

    cudaFuncSetAttribute(k_num, cudaFuncAttributeMaxDynamicSharedMemorySize, SMBYTES);

    k_prep<<<HH, 480>>>(logit, image, srcm, dstm, tgt);             // idx 0
    k_den<<<(NOFF2 + 14) / 15, 480>>>();                            // idx 1
    k_num<<<BB * BPB, NTHR, SMBYTES>>>(out);                        // idx 2
}

// round 15
// speedup vs baseline: 1.1827x; 1.0065x over previous
#include <cuda_runtime.h>

// Fixed shapes: B=2, C=3, H=320, W=480
#define HH   320
#define WW   480
#define BB   2
#define HWP  (HH * WW)          // 153600
#define SPAN 11
#define NOFF 23
#define NOFF2 (NOFF * NOFF)     // 529
#define NROWS (BB * HH)         // 640

#define PADW 512                // padded row stride
#define PADH (HH + 2 * SPAN)    // 342
#define PADSZ (PADH * PADW)     // 175104 per batch

#define SMW   502               // staged window width (uint2; 4016 B/row, 16B mult)
#define ROWB  (SMW * 8)         // 4016
#define WROWS 25                // max window rows (3 p-rows + 2*SPAN)
#define SMCNT (WROWS * SMW)     // 12550 uint2 = 100400 B
#define NTHR  576               // 2 groups x 288 (264 live each)
#define GRP   288
#define LIVE  264
#define LMAX  240               // max actives per row per parity
#define RPB   3                 // max p-rows per block
#define SMBYTES (SMCNT * 8 + 2 * RPB * LMAX * 2)   // 103280 -> 2 blocks/SM

#define NBLK  296               // 2 per SM x 148: exact single wave
#define BPB   148               // blocks per batch (24x3 rows + 124x2 rows)

#define NHALO 21504             // per batch: 342*512 - 320*480

// ---------------- scratch (static device globals) ----------------------------
__device__ uint2 g_pix8[BB * PADSZ];     // {r|g<<8|b<<16, y0|y1<<8|y2<<16 (|FF<<24 halo)}
__device__ float g_rps[HH][WW + 1];      // row prefix sums of M = sum_b (1-dst)
__device__ unsigned short g_actE[NROWS][LMAX]; // even-col active byte-offsets
__device__ unsigned short g_actO[NROWS][LMAX]; // odd-col active byte-offsets
__device__ int   g_cntE[NROWS];
__device__ int   g_cntO[NROWS];
__device__ float g_num[NOFF2];
__device__ float g_den[NOFF2];
__device__ float g_cep[HH];              // per-block CE partials
__device__ int   g_sync;                 // k_num completion counter (self-resetting)

// ---------------- helpers ----------------------------------------------------
__device__ __forceinline__ float warpReduceSum(float v) {
#pragma unroll
    for (int o = 16; o > 0; o >>= 1)
        v += __shfl_xor_sync(0xffffffffu, v, o);
    return v;
}

__device__ __forceinline__ float ex2f(float x) {
    float y;
    asm("ex2.approx.ftz.f32 %0, %1;" : "=f"(y) : "f"(x));
    return y;
}

// ---------------- kernel 1: prep (softmax/CE/pack/scan/lists + halo init) ------
__global__ void __launch_bounds__(480) k_prep(const float* __restrict__ logit,
                                              const float* __restrict__ image,
                                              const float* __restrict__ src,
                                              const float* __restrict__ dst,
                                              const int*   __restrict__ tgt) {
    __shared__ float s_wtot[15];
    __shared__ int   s_pcnt[BB][2][15];   // [batch][parity][warp]
    __shared__ float s_red[15];

    int i    = blockIdx.x;                // image row
    int j    = threadIdx.x;               // column
    int lane = j & 31;
    int w    = j >> 5;                    // warp 0..14
    int par  = j & 1;
    int idx  = i * WW + j;
    int pcol = (i + SPAN) * PADW + (j + SPAN);

    // ---- distributed halo init + accumulator zeroing (disjoint from interior)
    {
        int t = i * 480 + j;
        if (t < BB * NHALO) {
            int b = t / NHALO;
            int s = t - b * NHALO;
            int row, col;
            if (s < 11 * PADW) {                   // top halo rows 0..10
                row = s / PADW; col = s % PADW;
            } else if (s < 22 * PADW) {            // bottom halo rows 331..341
                int u = s - 11 * PADW;
                row = 331 + u / PADW; col = u % PADW;
            } else {                               // side cols of rows 11..330
                int u = s - 22 * PADW;
                row = 11 + u / 32;
                int c = u % 32;
                col = (c < 11) ? c : (480 + c);    // 0..10 and 491..511
            }
            uint2 v; v.x = 0u; v.y = 0xFF000000u;
            g_pix8[b * PADSZ + row * PADW + col] = v;
        }
        int t2 = t - BB * NHALO;
        if (t2 >= 0 && t2 < NOFF2) g_num[t2] = 0.0f;
    }

    float Msum = 0.0f, ceSum = 0.0f, dstSum = 0.0f;
    bool actv[BB];
#pragma unroll
    for (int b = 0; b < BB; b++) {
        int cb = b * 3 * HWP + idx;
        float l0 = logit[cb], l1 = logit[cb + HWP], l2 = logit[cb + 2 * HWP];
        float m  = fmaxf(l0, fmaxf(l1, l2));
        float e0 = __expf(l0 - m), e1 = __expf(l1 - m), e2 = __expf(l2 - m);
        float s  = e0 + e1 + e2;
        float inv = 1.0f / s;

        int   t  = tgt[b * HWP + idx];
        float lt = (t == 0) ? l0 : ((t == 1) ? l1 : l2);
        ceSum += m + __logf(s) - lt;

        float sv   = src[b * HWP + idx];
        float dv   = dst[b * HWP + idx];
        float mdst = 1.0f - dv;
        actv[b] = (sv * mdst) > 0.0f;

        float i0 = image[cb], i1 = image[cb + HWP], i2 = image[cb + 2 * HWP];
        unsigned r8 = __float2uint_rn(i0 * 255.0f);
        unsigned g8 = __float2uint_rn(i1 * 255.0f);
        unsigned b8 = __float2uint_rn(i2 * 255.0f);
        float y0 = e0 * inv, y1 = e1 * inv;
        int y0q = (int)__float2uint_rn(y0 * 255.0f);
        int y1q = (int)__float2uint_rn(y1 * 255.0f);
        int y2q = 255 - y0q - y1q;
        if (y2q < 0) y2q = 0;

        uint2 v;
        v.x = r8 | (g8 << 8) | (b8 << 16);
        v.y = (unsigned)y0q | ((unsigned)y1q << 8) | ((unsigned)y2q << 16);
        g_pix8[b * PADSZ + pcol] = v;      // byte3 of .y = 0 -> valid

        dstSum += dv;
        Msum   += mdst;
    }

    // ---- row inclusive prefix scan of Msum -> g_rps[i][*] ----
    float v = Msum;
#pragma unroll
    for (int o = 1; o < 32; o <<= 1) {
        float u = __shfl_up_sync(0xffffffffu, v, o);
        if (lane >= o) v += u;
    }
    if (lane == 31) s_wtot[w] = v;

    // ---- per (batch,parity) active ballots ----
    unsigned balE[BB], balO[BB];
#pragma unroll
    for (int b = 0; b < BB; b++) {
        balE[b] = __ballot_sync(0xffffffffu, actv[b] && par == 0);
        balO[b] = __ballot_sync(0xffffffffu, actv[b] && par == 1);
        if (lane == 0) {
            s_pcnt[b][0][w] = __popc(balE[b]);
            s_pcnt[b][1][w] = __popc(balO[b]);
        }
    }
    __syncthreads();

    if (j == 0) {
        float acc = 0.0f;
#pragma unroll
        for (int k = 0; k < 15; k++) { float c = s_wtot[k]; s_wtot[k] = acc; acc += c; }
#pragma unroll
        for (int b = 0; b < BB; b++) {
            int ie = 0, io = 0;
#pragma unroll
            for (int k = 0; k < 15; k++) {
                int ce = s_pcnt[b][0][k]; s_pcnt[b][0][k] = ie; ie += ce;
                int co = s_pcnt[b][1][k]; s_pcnt[b][1][k] = io; io += co;
            }
            g_cntE[b * HH + i] = ie;
            g_cntO[b * HH + i] = io;
        }
    }
    __syncthreads();

    if (j == 0) g_rps[i][0] = 0.0f;
    g_rps[i][j + 1] = v + s_wtot[w];

#pragma unroll
    for (int b = 0; b < BB; b++) {
        if (actv[b]) {
            unsigned bal = par ? balO[b] : balE[b];
            int pos = s_pcnt[b][par][w] + __popc(bal & ((1u << lane) - 1u));
            if (par) g_actO[b * HH + i][pos] = (unsigned short)(j << 3);
            else     g_actE[b * HH + i][pos] = (unsigned short)(j << 3);
        }
    }

    float pr = warpReduceSum(ceSum * dstSum);
    if (lane == 0) s_red[w] = pr;
    __syncthreads();
    if (w == 0) {
        float t2 = (lane < 15) ? s_red[lane] : 0.0f;
        t2 = warpReduceSum(t2);
        if (lane == 0) g_cep[i] = t2;
    }
}

// ---------------- kernel 2: denominators (warp per offset, rectangle sums) -----
__global__ void k_den() {               // grid=36, block=480
    int w    = blockIdx.x * 15 + (threadIdx.x >> 5);
    int lane = threadIdx.x & 31;
    if (w >= NOFF2) return;
    int dx = w / NOFF - SPAN;
    int dy = w % NOFF - SPAN;
    int r0 = (dx < 0) ? -dx : 0;
    int r1 = (dx > 0) ? HH - dx : HH;
    int c0 = (dy < 0) ? -dy : 0;
    int c1 = (dy > 0) ? WW - dy : WW;
    float s = 0.0f;
    for (int i = r0 + lane; i < r1; i += 32)
        s += g_rps[i][c1] - g_rps[i][c0];
    float tot = warpReduceSum(s);
    if (lane == 0) g_den[w] = tot;
}

// ---------------- numerator sweep (template on parity group) --------------------
// Core eval: dp4a folds the 0x4B000000 magic directly (s2, dp < 2^23). p's halo
// marker byte is OR'd in-register per pixel (p rows live inside the window).
// G=0: even pixels, E0 -> A (dyA=2m-11), E1 -> X (dyA+1)
// G=1: odd pixels,  E0 -> X (dyA-1),     E1 -> A
template<int G>
__device__ __forceinline__ void sweep2(const char* pb, const char* qb,
                                       const unsigned short* sal, int cnt,
                                       float& accA, float& stvA,
                                       float& accX, float& stvX) {
    const double KCd = -50.0 * 1.4426950408889634 / 65025.0;
    const float  KC  = (float)KCd;
    const float  KB  = (float)(-(double)KC * 8388608.0);
    const float  C1  = 8453633.0f;                 // 2^23 + 65025 (exact)
    const unsigned MAGIC = 0x4B000000u;
    const unsigned PMSK  = 0xFF000000u;
    const unsigned* sal32 = (const unsigned*)sal;

    int t = 0;
#pragma unroll 1
    for (; t + 2 <= cnt; t += 2) {
        unsigned pr = sal32[t >> 1];
        int ca = pr & 0xFFFFu;
        int cb = pr >> 16;
        uint2 p0 = *(const uint2*)(pb + ca);
        uint4 q0 = *(const uint4*)(qb + ca);
        uint2 p1 = *(const uint2*)(pb + cb);
        uint4 q1 = *(const uint4*)(qb + cb);
        unsigned py0 = p0.y | PMSK;
        unsigned py1 = p1.y | PMSK;

        unsigned d00  = __vabsdiffu4(p0.x, q0.x);
        unsigned s200 = __dp4a(d00, d00, MAGIC);
        unsigned dp00 = __dp4a(py0, q0.y, MAGIC);
        float k00  = ex2f(fmaf(__uint_as_float(s200), KC, KB));
        float tv00 = C1 - __uint_as_float(dp00);
        unsigned d01  = __vabsdiffu4(p0.x, q0.z);
        unsigned s201 = __dp4a(d01, d01, MAGIC);
        unsigned dp01 = __dp4a(py0, q0.w, MAGIC);
        float k01  = ex2f(fmaf(__uint_as_float(s201), KC, KB));
        float tv01 = C1 - __uint_as_float(dp01);
        unsigned d10  = __vabsdiffu4(p1.x, q1.x);
        unsigned s210 = __dp4a(d10, d10, MAGIC);
        unsigned dp10 = __dp4a(py1, q1.y, MAGIC);
        float k10  = ex2f(fmaf(__uint_as_float(s210), KC, KB));
        float tv10 = C1 - __uint_as_float(dp10);
        unsigned d11  = __vabsdiffu4(p1.x, q1.z);
        unsigned s211 = __dp4a(d11, d11, MAGIC);
        unsigned dp11 = __dp4a(py1, q1.w, MAGIC);
        float k11  = ex2f(fmaf(__uint_as_float(s211), KC, KB));
        float tv11 = C1 - __uint_as_float(dp11);

        if (G == 0) {
            accA = fmaf(k00, tv00, accA); stvA += tv00;
            accX = fmaf(k01, tv01, accX); stvX += tv01;
            accA = fmaf(k10, tv10, accA); stvA += tv10;
            accX = fmaf(k11, tv11, accX); stvX += tv11;
        } else {
            accX = fmaf(k00, tv00, accX); stvX += tv00;
            accA = fmaf(k01, tv01, accA); stvA += tv01;
            accX = fmaf(k10, tv10, accX); stvX += tv10;
            accA = fmaf(k11, tv11, accA); stvA += tv11;
        }
    }
    if (t < cnt) {
        int ca = sal[t];
        uint2 p0 = *(const uint2*)(pb + ca);
        uint4 q0 = *(const uint4*)(qb + ca);
        unsigned py0 = p0.y | PMSK;
        unsigned d00  = __vabsdiffu4(p0.x, q0.x);
        unsigned s200 = __dp4a(d00, d00, MAGIC);
        unsigned dp00 = __dp4a(py0, q0.y, MAGIC);
        float k00  = ex2f(fmaf(__uint_as_float(s200), KC, KB));
        float tv00 = C1 - __uint_as_float(dp00);
        unsigned d01  = __vabsdiffu4(p0.x, q0.z);
        unsigned s201 = __dp4a(d01, d01, MAGIC);
        unsigned dp01 = __dp4a(py0, q0.w, MAGIC);
        float k01  = ex2f(fmaf(__uint_as_float(s201), KC, KB));
        float tv01 = C1 - __uint_as_float(dp01);
        if (G == 0) {
            accA = fmaf(k00, tv00, accA); stvA += tv00;
            accX = fmaf(k01, tv01, accX); stvX += tv01;
        } else {
            accX = fmaf(k00, tv00, accX); stvX += tv00;
            accA = fmaf(k01, tv01, accA); stvA += tv01;
        }
    }
}

// ---------------- kernel 3: numerators + fused finalize --------------------------
// 296 blocks = 2/SM x 148 SM: EXACT single wave. Per batch, blocks 0..23 take
// 3 p-rows, 24..147 take 2 (24*3 + 124*2 = 320). Window staged once (<= 25
// rows, 100.4 KB); p rows read from the window with in-register halo-marker OR.
// Thread owns (dx, dy-pair); one aligned LDS.128 covers 2 dy bins. Last block
// performs the finalize and writes out[0].
__global__ void __launch_bounds__(NTHR) k_num(float* __restrict__ out) {
    extern __shared__ char smraw[];
    uint2* sm = (uint2*)smraw;                         // [<=25][SMW]
    unsigned short* slE = (unsigned short*)(sm + SMCNT);  // [RPB][LMAX]
    unsigned short* slO = slE + RPB * LMAX;               // [RPB][LMAX]
    __shared__ int s_last;
    __shared__ float s_fin[NTHR / 32];

    int bid = blockIdx.x;                              // 0..295
    int b   = bid / BPB;
    int k0  = bid - b * BPB;                           // 0..147
    int i0, nr;
    if (k0 < 24) { i0 = 3 * k0;              nr = 3; }
    else         { i0 = 72 + 2 * (k0 - 24);  nr = 2; }
    int rid0 = b * HH + i0;
    int tid = threadIdx.x;

    int cE[RPB], cO[RPB];
#pragma unroll
    for (int k = 0; k < RPB; k++) {
        cE[k] = (k < nr) ? g_cntE[rid0 + k] : 0;
        cO[k] = (k < nr) ? g_cntO[rid0 + k] : 0;
    }

    // stage window rows (padded rows i0 .. i0+nr+21)
    const uint2* grow = g_pix8 + (b * PADSZ + i0 * PADW);
    int nwr = nr + 22;
    for (int t = tid; t < nwr * SMW; t += NTHR) {
        int rr = t / SMW;
        int c  = t - rr * SMW;
        sm[rr * SMW + c] = grow[rr * PADW + c];
    }
    for (int k = 0; k < nr; k++) {
        for (int t = tid; t < cE[k]; t += NTHR) slE[k * LMAX + t] = g_actE[rid0 + k][t];
        for (int t = tid; t < cO[k]; t += NTHR) slO[k * LMAX + t] = g_actO[rid0 + k][t];
    }
    __syncthreads();

    int g = tid / GRP;                                 // 0 even, 1 odd pixels
    int u = tid - g * GRP;
    if (u < LIVE) {                                    // dead lanes skip sweep
        int dxi = u / 12;                              // 0..21
        int m   = u - dxi * 12;                        // 0..11 (dy-pair)
        int dx  = (dxi < SPAN) ? dxi - SPAN : dxi - SPAN + 1;

        float accA = 0.f, stvA = 0.f, accX = 0.f, stvX = 0.f;
        const char* pmb = (const char*)sm + SPAN * ROWB + SPAN * 8;  // p: window row SPAN
        const char* smb = (const char*)sm
            + ((dx + SPAN) * SMW + 2 * m) * 8 - (g ? 8 : 0);
        const unsigned short* lst = g ? slO : slE;
        const int* cc = g ? cO : cE;

#pragma unroll 1
        for (int k = 0; k < nr; k++) {
            const char* pb = pmb + k * ROWB;
            const char* qb = smb + k * ROWB;
            if (g == 0) sweep2<0>(pb, qb, lst + k * LMAX, cc[k], accA, stvA, accX, stvX);
            else        sweep2<1>(pb, qb, lst + k * LMAX, cc[k], accA, stvA, accX, stvX);
        }

        const float INV = 1.0f / 65025.0f;
        int dyA = 2 * m - SPAN;                        // odd, always live
        {
            float kxy = __expf((float)(dx * dx + dyA * dyA) * (-1.0f / 72.0f));
            atomicAdd(&g_num[(dx + SPAN) * NOFF + (dyA + SPAN)],
                      fmaf(kxy, stvA, accA) * INV);
        }
        int dyX = g ? (dyA - 1) : (dyA + 1);
        if (dyX != 0 && dyX >= -SPAN && dyX <= SPAN) {
            float kxy = __expf((float)(dx * dx + dyX * dyX) * (-1.0f / 72.0f));
            atomicAdd(&g_num[(dx + SPAN) * NOFF + (dyX + SPAN)],
                      fmaf(kxy, stvX, accX) * INV);
        }
    }

    // ---- last-block finalize ----
    __threadfence();
    if (tid == 0)
        s_last = (atomicAdd(&g_sync, 1) == (int)gridDim.x - 1) ? 1 : 0;
    __syncthreads();
    if (!s_last) return;
    __threadfence();

    float v = 0.0f;
    for (int d = tid; d < NOFF2; d += NTHR) {
        int dx = d / NOFF - SPAN;
        int dy = d % NOFF - SPAN;
        if (dx != 0 && dy != 0)
            v += __fdividef(__ldcg(&g_num[d]), g_den[d]);
    }
    v *= (0.15f / (float)NOFF2);
    float ce = 0.0f;
    for (int t = tid; t < HH; t += NTHR) ce += g_cep[t];
    v += ce * (1.0f / ((float)BB * BB * HWP));

    int lane = tid & 31, w = tid >> 5;
    v = warpReduceSum(v);
    if (lane == 0) s_fin[w] = v;
    __syncthreads();
    if (w == 0) {
        float t2 = (lane < (NTHR >> 5)) ? s_fin[lane] : 0.0f;
        t2 = warpReduceSum(t2);
        if (lane == 0) {
            out[0] = t2;
            g_sync = 0;                                // reset for next replay
        }
    }
}

// ---------------- launch ----------------------------------------------------------
extern "C" void kernel_launch(void* const* d_in, const int* in_sizes, int n_in,
                              void* d_out, int out_size) {
    const float* logit = (const float*)d_in[0];
    const float* image = (const float*)d_in[1];
    const float* srcm  = (const float*)d_in[2];
    const float* dstm  = (const float*)d_in[3];
    const int*   tgt   = (const int*)d_in[4];
    float* out = (float*)d_out;

    cudaFuncSetAttribute(k_num, cudaFuncAttributeMaxDynamicSharedMemorySize, SMBYTES);

    k_prep<<<HH, 480>>>(logit, image, srcm, dstm, tgt);             // idx 0
    k_den<<<(NOFF2 + 14) / 15, 480>>>();                            // idx 1
    k_num<<<NBLK, NTHR, SMBYTES>>>(out);                            // idx 2
}

// round 16
// speedup vs baseline: 1.2836x; 1.0853x over previous
#include <cuda_runtime.h>

// Fixed shapes: B=2, C=3, H=320, W=480
#define HH   320
#define WW   480
#define BB   2
#define HWP  (HH * WW)          // 153600
#define SPAN 11
#define NOFF 23
#define NOFF2 (NOFF * NOFF)     // 529
#define NROWS (BB * HH)         // 640

#define PADW 512                // padded row stride
#define PADH (HH + 2 * SPAN)    // 342
#define PADSZ (PADH * PADW)     // 175104 per batch

#define SMW 504                 // staged window width (uint2)
#define WROWS 24                // window rows: 2 p-rows +/- SPAN
#define SMCNT2 (WROWS * SMW)    // 12096 uint2 = 96768 B
#define NTHR 576                // 2 groups x 288 (264 live each)
#define GRP  288
#define LIVE 264
#define LMAX 240                // max actives per row per parity
#define SMBYTES (SMCNT2 * 8 + 2 * SMW * 8 + 4 * LMAX * 2)

#define NHALO 21504             // per batch: 342*512 - 320*480

// ---------------- scratch (static device globals) ----------------------------
__device__ uint2 g_pix8[BB * PADSZ];     // {r|g<<8|b<<16, y0|y1<<8|y2<<16 (|FF<<24 halo)}
__device__ float g_rps[HH][WW + 1];      // row prefix sums of M = sum_b (1-dst)
__device__ unsigned short g_actE[NROWS][LMAX]; // even-col active byte-offsets
__device__ unsigned short g_actO[NROWS][LMAX]; // odd-col active byte-offsets
__device__ int   g_cntE[NROWS];
__device__ int   g_cntO[NROWS];
__device__ float g_num[NOFF2];
__device__ float g_den[NOFF2];
__device__ float g_cep[HH];              // per-block CE partials
__device__ int   g_sync;                 // k_num completion counter (self-resetting)

// ---------------- helpers ----------------------------------------------------
__device__ __forceinline__ float warpReduceSum(float v) {
#pragma unroll
    for (int o = 16; o > 0; o >>= 1)
        v += __shfl_xor_sync(0xffffffffu, v, o);
    return v;
}

__device__ __forceinline__ float ex2f(float x) {
    float y;
    asm("ex2.approx.ftz.f32 %0, %1;" : "=f"(y) : "f"(x));
    return y;
}

// ---------------- kernel 1: prep (softmax/CE/pack/scan/lists + halo init) ------
__global__ void __launch_bounds__(480) k_prep(const float* __restrict__ logit,
                                              const float* __restrict__ image,
                                              const float* __restrict__ src,
                                              const float* __restrict__ dst,
                                              const int*   __restrict__ tgt) {
    __shared__ float s_wtot[15];
    __shared__ int   s_pcnt[BB][2][15];   // [batch][parity][warp]
    __shared__ float s_red[15];

    int i    = blockIdx.x;                // image row
    int j    = threadIdx.x;               // column
    int lane = j & 31;
    int w    = j >> 5;                    // warp 0..14
    int par  = j & 1;
    int idx  = i * WW + j;
    int pcol = (i + SPAN) * PADW + (j + SPAN);

    // ---- distributed halo init + accumulator zeroing (disjoint from interior)
    {
        int t = i * 480 + j;
        if (t < BB * NHALO) {
            int b = t / NHALO;
            int s = t - b * NHALO;
            int row, col;
            if (s < 11 * PADW) {                   // top halo rows 0..10
                row = s / PADW; col = s % PADW;
            } else if (s < 22 * PADW) {            // bottom halo rows 331..341
                int u = s - 11 * PADW;
                row = 331 + u / PADW; col = u % PADW;
            } else {                               // side cols of rows 11..330
                int u = s - 22 * PADW;
                row = 11 + u / 32;
                int c = u % 32;
                col = (c < 11) ? c : (480 + c);    // 0..10 and 491..511
            }
            uint2 v; v.x = 0u; v.y = 0xFF000000u;
            g_pix8[b * PADSZ + row * PADW + col] = v;
        }
        int t2 = t - BB * NHALO;
        if (t2 >= 0 && t2 < NOFF2) g_num[t2] = 0.0f;
    }

    float Msum = 0.0f, ceSum = 0.0f, dstSum = 0.0f;
    bool actv[BB];
#pragma unroll
    for (int b = 0; b < BB; b++) {
        int cb = b * 3 * HWP + idx;
        float l0 = logit[cb], l1 = logit[cb + HWP], l2 = logit[cb + 2 * HWP];
        float m  = fmaxf(l0, fmaxf(l1, l2));
        float e0 = __expf(l0 - m), e1 = __expf(l1 - m), e2 = __expf(l2 - m);
        float s  = e0 + e1 + e2;
        float inv = 1.0f / s;

        int   t  = tgt[b * HWP + idx];
        float lt = (t == 0) ? l0 : ((t == 1) ? l1 : l2);
        ceSum += m + __logf(s) - lt;

        float sv   = src[b * HWP + idx];
        float dv   = dst[b * HWP + idx];
        float mdst = 1.0f - dv;
        actv[b] = (sv * mdst) > 0.0f;

        float i0 = image[cb], i1 = image[cb + HWP], i2 = image[cb + 2 * HWP];
        unsigned r8 = __float2uint_rn(i0 * 255.0f);
        unsigned g8 = __float2uint_rn(i1 * 255.0f);
        unsigned b8 = __float2uint_rn(i2 * 255.0f);
        float y0 = e0 * inv, y1 = e1 * inv;
        int y0q = (int)__float2uint_rn(y0 * 255.0f);
        int y1q = (int)__float2uint_rn(y1 * 255.0f);
        int y2q = 255 - y0q - y1q;
        if (y2q < 0) y2q = 0;

        uint2 v;
        v.x = r8 | (g8 << 8) | (b8 << 16);
        v.y = (unsigned)y0q | ((unsigned)y1q << 8) | ((unsigned)y2q << 16);
        g_pix8[b * PADSZ + pcol] = v;      // byte3 of .y = 0 -> valid

        dstSum += dv;
        Msum   += mdst;
    }

    // ---- row inclusive prefix scan of Msum -> g_rps[i][*] ----
    float v = Msum;
#pragma unroll
    for (int o = 1; o < 32; o <<= 1) {
        float u = __shfl_up_sync(0xffffffffu, v, o);
        if (lane >= o) v += u;
    }
    if (lane == 31) s_wtot[w] = v;

    // ---- per (batch,parity) active ballots ----
    unsigned balE[BB], balO[BB];
#pragma unroll
    for (int b = 0; b < BB; b++) {
        balE[b] = __ballot_sync(0xffffffffu, actv[b] && par == 0);
        balO[b] = __ballot_sync(0xffffffffu, actv[b] && par == 1);
        if (lane == 0) {
            s_pcnt[b][0][w] = __popc(balE[b]);
            s_pcnt[b][1][w] = __popc(balO[b]);
        }
    }
    __syncthreads();

    if (j == 0) {
        float acc = 0.0f;
#pragma unroll
        for (int k = 0; k < 15; k++) { float c = s_wtot[k]; s_wtot[k] = acc; acc += c; }
#pragma unroll
        for (int b = 0; b < BB; b++) {
            int ie = 0, io = 0;
#pragma unroll
            for (int k = 0; k < 15; k++) {
                int ce = s_pcnt[b][0][k]; s_pcnt[b][0][k] = ie; ie += ce;
                int co = s_pcnt[b][1][k]; s_pcnt[b][1][k] = io; io += co;
            }
            g_cntE[b * HH + i] = ie;
            g_cntO[b * HH + i] = io;
        }
    }
    __syncthreads();

    if (j == 0) g_rps[i][0] = 0.0f;
    g_rps[i][j + 1] = v + s_wtot[w];

#pragma unroll
    for (int b = 0; b < BB; b++) {
        if (actv[b]) {
            unsigned bal = par ? balO[b] : balE[b];
            int pos = s_pcnt[b][par][w] + __popc(bal & ((1u << lane) - 1u));
            if (par) g_actO[b * HH + i][pos] = (unsigned short)(j << 3);
            else     g_actE[b * HH + i][pos] = (unsigned short)(j << 3);
        }
    }

    float pr = warpReduceSum(ceSum * dstSum);
    if (lane == 0) s_red[w] = pr;
    __syncthreads();
    if (w == 0) {
        float t2 = (lane < 15) ? s_red[lane] : 0.0f;
        t2 = warpReduceSum(t2);
        if (lane == 0) g_cep[i] = t2;
    }
}

// ---------------- kernel 2: denominators (warp per offset, rectangle sums) -----
__global__ void k_den() {               // grid=36, block=480
    int w    = blockIdx.x * 15 + (threadIdx.x >> 5);
    int lane = threadIdx.x & 31;
    if (w >= NOFF2) return;
    int dx = w / NOFF - SPAN;
    int dy = w % NOFF - SPAN;
    int r0 = (dx < 0) ? -dx : 0;
    int r1 = (dx > 0) ? HH - dx : HH;
    int c0 = (dy < 0) ? -dy : 0;
    int c1 = (dy > 0) ? WW - dy : WW;
    float s = 0.0f;
    for (int i = r0 + lane; i < r1; i += 32)
        s += g_rps[i][c1] - g_rps[i][c0];
    float tot = warpReduceSum(s);
    if (lane == 0) g_den[w] = tot;
}

// ---------------- numerator sweep (template on parity group) --------------------
// Core eval: 8 inst — dp4a folds the 0x4B000000 magic directly (s2, dp < 2^23).
// G=0: even pixels, E0 -> A (dyA=2m-11), E1 -> X (dyA+1)
// G=1: odd pixels,  E0 -> X (dyA-1),     E1 -> A
#define EVAL_PIXEL(p, q, accA, stvA, accX, stvX, G_) do {                     \
    unsigned dA_  = __vabsdiffu4((p).x, (q).x);                               \
    unsigned s2A_ = __dp4a(dA_, dA_, 0x4B000000u);                            \
    unsigned dpA_ = __dp4a((p).y, (q).y, 0x4B000000u);                        \
    float kA_  = ex2f(fmaf(__uint_as_float(s2A_), KC, KB));                   \
    float tvA_ = C1 - __uint_as_float(dpA_);                                  \
    unsigned dB_  = __vabsdiffu4((p).x, (q).z);                               \
    unsigned s2B_ = __dp4a(dB_, dB_, 0x4B000000u);                            \
    unsigned dpB_ = __dp4a((p).y, (q).w, 0x4B000000u);                        \
    float kB_  = ex2f(fmaf(__uint_as_float(s2B_), KC, KB));                   \
    float tvB_ = C1 - __uint_as_float(dpB_);                                  \
    if (G_ == 0) {                                                            \
        accA = fmaf(kA_, tvA_, accA); stvA += tvA_;                           \
        accX = fmaf(kB_, tvB_, accX); stvX += tvB_;                           \
    } else {                                                                  \
        accX = fmaf(kA_, tvA_, accX); stvX += tvA_;                           \
        accA = fmaf(kB_, tvB_, accA); stvA += tvB_;                           \
    }                                                                         \
} while (0)

template<int G>
__device__ __forceinline__ void sweep2(const char* pb, const char* qb,
                                       const unsigned short* sal, int cnt,
                                       float& accA, float& stvA,
                                       float& accX, float& stvX) {
    const double KCd = -50.0 * 1.4426950408889634 / 65025.0;
    const float  KC  = (float)KCd;
    const float  KB  = (float)(-(double)KC * 8388608.0);
    const float  C1  = 8453633.0f;                 // 2^23 + 65025 (exact)
    const unsigned* sal32 = (const unsigned*)sal;

    int t = 0;
#pragma unroll 1
    for (; t + 4 <= cnt; t += 4) {                 // x4 pixel unroll
        unsigned w0 = sal32[t >> 1];
        unsigned w1 = sal32[(t >> 1) + 1];
        int c0 = w0 & 0xFFFFu, c1 = w0 >> 16;
        int c2 = w1 & 0xFFFFu, c3 = w1 >> 16;
        uint2 p0 = *(const uint2*)(pb + c0);
        uint4 q0 = *(const uint4*)(qb + c0);
        uint2 p1 = *(const uint2*)(pb + c1);
        uint4 q1 = *(const uint4*)(qb + c1);
        uint2 p2 = *(const uint2*)(pb + c2);
        uint4 q2 = *(const uint4*)(qb + c2);
        uint2 p3 = *(const uint2*)(pb + c3);
        uint4 q3 = *(const uint4*)(qb + c3);
        EVAL_PIXEL(p0, q0, accA, stvA, accX, stvX, G);
        EVAL_PIXEL(p1, q1, accA, stvA, accX, stvX, G);
        EVAL_PIXEL(p2, q2, accA, stvA, accX, stvX, G);
        EVAL_PIXEL(p3, q3, accA, stvA, accX, stvX, G);
    }
    if (t + 2 <= cnt) {
        unsigned w0 = sal32[t >> 1];
        int c0 = w0 & 0xFFFFu, c1 = w0 >> 16;
        uint2 p0 = *(const uint2*)(pb + c0);
        uint4 q0 = *(const uint4*)(qb + c0);
        uint2 p1 = *(const uint2*)(pb + c1);
        uint4 q1 = *(const uint4*)(qb + c1);
        EVAL_PIXEL(p0, q0, accA, stvA, accX, stvX, G);
        EVAL_PIXEL(p1, q1, accA, stvA, accX, stvX, G);
        t += 2;
    }
    if (t < cnt) {
        int c0 = sal[t];
        uint2 p0 = *(const uint2*)(pb + c0);
        uint4 q0 = *(const uint4*)(qb + c0);
        EVAL_PIXEL(p0, q0, accA, stvA, accX, stvX, G);
    }
}

// ---------------- kernel 3: numerators + fused finalize --------------------------
// Block = 2 p-rows (320 blocks, 2/SM). Group 0 sweeps even-column actives,
// group 1 odd-column; thread owns (dx, dy-pair m), one aligned LDS.128 covers
// 2 dy bins. Last block performs the finalize and writes out[0].
__global__ void __launch_bounds__(NTHR) k_num(float* __restrict__ out) {
    extern __shared__ char smraw[];
    uint2* sm = (uint2*)smraw;                         // [24][SMW]
    uint2* pm = sm + SMCNT2;                           // [2][SMW] masked p rows
    unsigned short* slE0 = (unsigned short*)(pm + 2 * SMW);
    unsigned short* slE1 = slE0 + LMAX;
    unsigned short* slO0 = slE1 + LMAX;
    unsigned short* slO1 = slO0 + LMAX;
    __shared__ int s_last;
    __shared__ float s_fin[NTHR / 32];

    int rid2 = blockIdx.x;                             // 0..319
    int b    = rid2 / (HH / 2);
    int rp   = rid2 - b * (HH / 2);
    int r0   = rp * 2;
    int rid0 = b * HH + r0;
    int cE0 = g_cntE[rid0], cE1 = g_cntE[rid0 + 1];
    int cO0 = g_cntO[rid0], cO1 = g_cntO[rid0 + 1];
    int tid = threadIdx.x;

    const uint2* grow = g_pix8 + (b * PADSZ + r0 * PADW);
    if (tid < SMW) {
#pragma unroll
        for (int rr = 0; rr < WROWS; rr++)
            sm[rr * SMW + tid] = grow[rr * PADW + tid];
        uint2 v0 = grow[SPAN * PADW + tid];       v0.y |= 0xFF000000u; pm[tid] = v0;
        uint2 v1 = grow[(SPAN + 1) * PADW + tid]; v1.y |= 0xFF000000u; pm[SMW + tid] = v1;
    }
    for (int t = tid; t < cE0; t += NTHR) slE0[t] = g_actE[rid0][t];
    for (int t = tid; t < cE1; t += NTHR) slE1[t] = g_actE[rid0 + 1][t];
    for (int t = tid; t < cO0; t += NTHR) slO0[t] = g_actO[rid0][t];
    for (int t = tid; t < cO1; t += NTHR) slO1[t] = g_actO[rid0 + 1][t];
    __syncthreads();

    int g = tid / GRP;                                 // 0 even, 1 odd pixels
    int u = tid - g * GRP;
    if (u < LIVE) {                                    // dead lanes skip sweep
        int dxi = u / 12;                              // 0..21
        int m   = u - dxi * 12;                        // 0..11 (dy-pair)
        int dx  = (dxi < SPAN) ? dxi - SPAN : dxi - SPAN + 1;

        const char* pb0 = (const char*)pm + SPAN * 8;
        const char* qb0 = (const char*)sm + ((SPAN + dx) * SMW + 2 * m) * 8 - (g ? 8 : 0);

        float accA = 0.f, stvA = 0.f, accX = 0.f, stvX = 0.f;
        if (g == 0) {
            sweep2<0>(pb0, qb0, slE0, cE0, accA, stvA, accX, stvX);
            sweep2<0>(pb0 + SMW * 8, qb0 + SMW * 8, slE1, cE1, accA, stvA, accX, stvX);
        } else {
            sweep2<1>(pb0, qb0, slO0, cO0, accA, stvA, accX, stvX);
            sweep2<1>(pb0 + SMW * 8, qb0 + SMW * 8, slO1, cO1, accA, stvA, accX, stvX);
        }

        const float INV = 1.0f / 65025.0f;
        int dyA = 2 * m - SPAN;                        // odd, always live
        {
            float kxy = __expf((float)(dx * dx + dyA * dyA) * (-1.0f / 72.0f));
            atomicAdd(&g_num[(dx + SPAN) * NOFF + (dyA + SPAN)],
                      fmaf(kxy, stvA, accA) * INV);
        }
        int dyX = g ? (dyA - 1) : (dyA + 1);
        if (dyX != 0 && dyX >= -SPAN && dyX <= SPAN) {
            float kxy = __expf((float)(dx * dx + dyX * dyX) * (-1.0f / 72.0f));
            atomicAdd(&g_num[(dx + SPAN) * NOFF + (dyX + SPAN)],
                      fmaf(kxy, stvX, accX) * INV);
        }
    }

    // ---- last-block finalize ----
    __threadfence();
    if (tid == 0)
        s_last = (atomicAdd(&g_sync, 1) == (int)gridDim.x - 1) ? 1 : 0;
    __syncthreads();
    if (!s_last) return;
    __threadfence();

    float v = 0.0f;
    for (int d = tid; d < NOFF2; d += NTHR) {
        int dx = d / NOFF - SPAN;
        int dy = d % NOFF - SPAN;
        if (dx != 0 && dy != 0)
            v += __fdividef(__ldcg(&g_num[d]), g_den[d]);
    }
    v *= (0.15f / (float)NOFF2);
    float ce = 0.0f;
    for (int t = tid; t < HH; t += NTHR) ce += g_cep[t];
    v += ce * (1.0f / ((float)BB * BB * HWP));

    int lane = tid & 31, w = tid >> 5;
    v = warpReduceSum(v);
    if (lane == 0) s_fin[w] = v;
    __syncthreads();
    if (w == 0) {
        float t2 = (lane < (NTHR >> 5)) ? s_fin[lane] : 0.0f;
        t2 = warpReduceSum(t2);
        if (lane == 0) {
            out[0] = t2;
            g_sync = 0;                                // reset for next replay
        }
    }
}

// ---------------- launch ----------------------------------------------------------
extern "C" void kernel_launch(void* const* d_in, const int* in_sizes, int n_in,
                              void* d_out, int out_size) {
    const float* logit = (const float*)d_in[0];
    const float* image = (const float*)d_in[1];
    const float* srcm  = (const float*)d_in[2];
    const float* dstm  = (const float*)d_in[3];
    const int*   tgt   = (const int*)d_in[4];
    float* out = (float*)d_out;

    cudaFuncSetAttribute(k_num, cudaFuncAttributeMaxDynamicSharedMemorySize, SMBYTES);

    k_prep<<<HH, 480>>>(logit, image, srcm, dstm, tgt);             // idx 0
    k_den<<<(NOFF2 + 14) / 15, 480>>>();                            // idx 1
    k_num<<<NROWS / 2, NTHR, SMBYTES>>>(out);                       // idx 2
}